// round 8
// baseline (speedup 1.0000x reference)
#include <cuda_runtime.h>

// Problem constants
#define Tn 336
#define Fn 12
#define Hn 50
#define Bn 4096
#define BC 32          // batch rows per CTA
#define NTHREADS 256
#define HPAD 52        // h row stride (16B-multiple)
#define RPG 8          // rows per group (4 groups x 2 warps)

// shared memory float offsets.
// Each weight matrix staged as j-pair A/B halves:
//   A[(p*50+u)*4 + {i_j0,i_j1,f_j0,f_j1}], B same for gates (g,o).
// B-half sits at a fixed float offset from A (compile-time immediate).
#define W0XA_OFF 0        // layer0 x-part A: 1200   (B at +1200)
#define W0HA_OFF 2400     // layer0 h-part A: 5000   (B at +5000)
#define W1IA_OFF 12400    // layer1 input(h0)        (B at +5000)
#define W1RA_OFF 22400    // layer1 recurrent(h1)
#define W2IA_OFF 32400
#define W2RA_OFF 42400
#define HS_OFF   52400    // h state  3 * 32 * 52 = 4992
#define XS_OFF   57392    // x tile   32 * 12 = 384
#define SMEM_FLOATS 57776
#define SMEM_BYTES (SMEM_FLOATS * 4)

typedef unsigned long long u64;

// packed dual-fp32 FMA (sm_103a FFMA2): z += w * h (elementwise, 2 fp32 lanes)
__device__ __forceinline__ void ffma2(u64& z, const u64 w, const u64 h) {
    asm("fma.rn.f32x2 %0, %1, %2, %0;" : "+l"(z) : "l"(w), "l"(h));
}
__device__ __forceinline__ void unpack2(const u64 v, float& lo, float& hi) {
    asm("mov.b64 {%0, %1}, %2;" : "=f"(lo), "=f"(hi) : "l"(v));
}

__device__ __forceinline__ float sigmoidf_(float v) {
    return 1.0f / (1.0f + __expf(-v));
}
// precise-enough tanh: 1 - 2/(1+e^{2x}); ~1e-7 rel err
__device__ __forceinline__ float tanhf_(float v) {
    const float e = __expf(2.0f * v);
    return 1.0f - 2.0f / (e + 1.0f);
}

// named barrier for a 2-warp group (ids 1..4; 0 reserved for __syncthreads)
__device__ __forceinline__ void barg(int id) {
    asm volatile("bar.sync %0, 64;" :: "r"(id) : "memory");
}

// 25 j-pairs over a 50-long vector (stride HPAD). BO = float offset A->B half.
template<int BO>
__device__ __forceinline__ void accH(u64 zi[RPG], u64 zf[RPG], u64 zg[RPG], u64 zo[RPG],
                                     const float* __restrict__ WA,
                                     const float* __restrict__ hb, int u)
{
    const float* wa = WA + u*4;
    const float* hq = hb;
#pragma unroll 1
    for (int p = 0; p < 24; p += 2) {
        const ulonglong2 wa0 = *(const ulonglong2*)(wa);
        const ulonglong2 wb0 = *(const ulonglong2*)(wa + BO);
        const ulonglong2 wa1 = *(const ulonglong2*)(wa + 200);
        const ulonglong2 wb1 = *(const ulonglong2*)(wa + BO + 200);
#pragma unroll
        for (int r = 0; r < RPG; r++) {
            const ulonglong2 hv = *(const ulonglong2*)(hq + r*HPAD);
            ffma2(zi[r], wa0.x, hv.x); ffma2(zf[r], wa0.y, hv.x);
            ffma2(zg[r], wb0.x, hv.x); ffma2(zo[r], wb0.y, hv.x);
            ffma2(zi[r], wa1.x, hv.y); ffma2(zf[r], wa1.y, hv.y);
            ffma2(zg[r], wb1.x, hv.y); ffma2(zo[r], wb1.y, hv.y);
        }
        wa += 400; hq += 4;
    }
    // remainder pair p=24 (j=48,49)
    const ulonglong2 waR = *(const ulonglong2*)(wa);
    const ulonglong2 wbR = *(const ulonglong2*)(wa + BO);
#pragma unroll
    for (int r = 0; r < RPG; r++) {
        const u64 hp_ = *(const u64*)(hq + r*HPAD);
        ffma2(zi[r], waR.x, hp_); ffma2(zf[r], waR.y, hp_);
        ffma2(zg[r], wbR.x, hp_); ffma2(zo[r], wbR.y, hp_);
    }
}

// 6 j-pairs over the 12-long x vector (stride Fn). BO = float offset A->B half.
template<int BO>
__device__ __forceinline__ void accX(u64 zi[RPG], u64 zf[RPG], u64 zg[RPG], u64 zo[RPG],
                                     const float* __restrict__ WA,
                                     const float* __restrict__ xr, int u)
{
    const float* wa = WA + u*4;
    const float* xq = xr;
#pragma unroll 1
    for (int p = 0; p < 6; p += 2) {
        const ulonglong2 wa0 = *(const ulonglong2*)(wa);
        const ulonglong2 wb0 = *(const ulonglong2*)(wa + BO);
        const ulonglong2 wa1 = *(const ulonglong2*)(wa + 200);
        const ulonglong2 wb1 = *(const ulonglong2*)(wa + BO + 200);
#pragma unroll
        for (int r = 0; r < RPG; r++) {
            const ulonglong2 hv = *(const ulonglong2*)(xq + r*Fn);
            ffma2(zi[r], wa0.x, hv.x); ffma2(zf[r], wa0.y, hv.x);
            ffma2(zg[r], wb0.x, hv.x); ffma2(zo[r], wb0.y, hv.x);
            ffma2(zi[r], wa1.x, hv.y); ffma2(zf[r], wa1.y, hv.y);
            ffma2(zg[r], wb1.x, hv.y); ffma2(zo[r], wb1.y, hv.y);
        }
        wa += 400; xq += 4;
    }
}

__global__ void __launch_bounds__(NTHREADS, 1)
lstm_fused(const float* __restrict__ x,
           const float* __restrict__ Wih0, const float* __restrict__ Whh0,
           const float* __restrict__ bih0, const float* __restrict__ bhh0,
           const float* __restrict__ Wih1, const float* __restrict__ Whh1,
           const float* __restrict__ bih1, const float* __restrict__ bhh1,
           const float* __restrict__ Wih2, const float* __restrict__ Whh2,
           const float* __restrict__ bih2, const float* __restrict__ bhh2,
           const float* __restrict__ Wlin, const float* __restrict__ blin,
           float* __restrict__ out)
{
    extern __shared__ float sm[];
    float* HS = sm + HS_OFF;   // [3][BC][HPAD]
    float* XS = sm + XS_OFF;   // [BC][12]

    const int tid   = threadIdx.x;
    const int lane  = tid & 31;
    const int wid   = tid >> 5;
    const int grp   = wid >> 1;               // 0..3
    const int bid   = grp + 1;                // named barrier id
    const int r0    = grp * RPG;              // row base (8 rows)
    const int u     = (wid & 1) * 32 + lane;  // unit id
    const bool act  = (u < Hn);
    const int gtid  = tid & 63;               // thread id within group

    // ---- stage weights: j-pair A/B halves ----
    // layer0 x-part: 6 pairs from Wih0 [4H x 12]
    for (int idx = tid; idx < 1200; idx += NTHREADS) {
        const int uu = (idx >> 2) % 50;
        const int p  = idx / 200;
        const int jj = idx & 1;
        const int gh = (idx >> 1) & 1;
        const int j  = 2*p + jj;
        sm[W0XA_OFF + idx]        = Wih0[((0 + gh)*50 + uu)*12 + j];
        sm[W0XA_OFF + 1200 + idx] = Wih0[((2 + gh)*50 + uu)*12 + j];
    }
    // 25-pair blocks from [4H x 50] sources
    {
        const float* srcs[5] = { Whh0, Wih1, Whh1, Wih2, Whh2 };
        const int offA[5] = { W0HA_OFF, W1IA_OFF, W1RA_OFF, W2IA_OFF, W2RA_OFF };
#pragma unroll 1
        for (int s = 0; s < 5; s++) {
            const float* Wsrc = srcs[s];
            float* A = sm + offA[s];
            for (int idx = tid; idx < 5000; idx += NTHREADS) {
                const int uu = (idx >> 2) % 50;
                const int p  = idx / 200;
                const int jj = idx & 1;
                const int gh = (idx >> 1) & 1;
                const int j  = 2*p + jj;
                A[idx]        = Wsrc[((0 + gh)*50 + uu)*50 + j];
                A[5000 + idx] = Wsrc[((2 + gh)*50 + uu)*50 + j];
            }
        }
    }
    for (int idx = tid; idx < 3*BC*HPAD; idx += NTHREADS) HS[idx] = 0.0f;

    // biases as plain floats (added in the horizontal reduction)
    float bi0=0.f,bf0=0.f,bg0=0.f,bo0=0.f;
    float bi1=0.f,bf1=0.f,bg1=0.f,bo1=0.f;
    float bi2=0.f,bf2=0.f,bg2=0.f,bo2=0.f;
    if (act) {
        bi0 = bih0[u]       + bhh0[u];
        bf0 = bih0[50 + u]  + bhh0[50 + u];
        bg0 = bih0[100 + u] + bhh0[100 + u];
        bo0 = bih0[150 + u] + bhh0[150 + u];
        bi1 = bih1[u]       + bhh1[u];
        bf1 = bih1[50 + u]  + bhh1[50 + u];
        bg1 = bih1[100 + u] + bhh1[100 + u];
        bo1 = bih1[150 + u] + bhh1[150 + u];
        bi2 = bih2[u]       + bhh2[u];
        bf2 = bih2[50 + u]  + bhh2[50 + u];
        bg2 = bih2[100 + u] + bhh2[100 + u];
        bo2 = bih2[150 + u] + bhh2[150 + u];
    }

    float c0[RPG], c1[RPG], c2[RPG];
#pragma unroll
    for (int r = 0; r < RPG; r++) { c0[r] = 0.f; c1[r] = 0.f; c2[r] = 0.f; }

    const long long bbase = (long long)blockIdx.x * BC;
    const float* xb = x + bbase * (Tn * Fn);

    // group loads its own 8 rows x 12 = 96 x-values with 64 threads (2 passes)
    const int xrow0 = r0 + gtid / Fn;
    const int xcol0 = gtid % Fn;
    const int xrow1 = r0 + (gtid + 64) / Fn;
    const int xcol1 = (gtid + 64) % Fn;

    __syncthreads();

    float* HS0 = HS + 0*(BC*HPAD) + r0*HPAD;
    float* HS1 = HS + 1*(BC*HPAD) + r0*HPAD;
    float* HS2 = HS + 2*(BC*HPAD) + r0*HPAD;
    float* XSg = XS + r0*Fn;

    for (int t = 0; t < Tn; t++) {
        // ---- group-local x tile load: 8 rows x 12 ----
        XSg[gtid]      = xb[xrow0*(Tn*Fn) + t*Fn + xcol0];
        if (gtid + 64 < RPG*Fn)
            XSg[gtid + 64] = xb[xrow1*(Tn*Fn) + t*Fn + xcol1];
        barg(bid);

        float hn[RPG];
        u64 zi[RPG], zf[RPG], zg[RPG], zo[RPG];

        // ================= layer 0 =================
        if (act) {
#pragma unroll
            for (int r = 0; r < RPG; r++) { zi[r]=0; zf[r]=0; zg[r]=0; zo[r]=0; }
            accX<1200>(zi, zf, zg, zo, sm + W0XA_OFF, XSg, u);
            accH<5000>(zi, zf, zg, zo, sm + W0HA_OFF, HS0, u);
#pragma unroll
            for (int r = 0; r < RPG; r++) {
                float a, b;
                unpack2(zi[r], a, b); const float si = a + b + bi0;
                unpack2(zf[r], a, b); const float sf = a + b + bf0;
                unpack2(zg[r], a, b); const float sg = a + b + bg0;
                unpack2(zo[r], a, b); const float so = a + b + bo0;
                const float ig = sigmoidf_(si);
                const float fg = sigmoidf_(sf);
                const float gg = tanhf_(sg);
                const float og = sigmoidf_(so);
                c0[r] = fg * c0[r] + ig * gg;
                hn[r] = og * tanhf_(c0[r]);
            }
        }
        barg(bid);
        if (act) {
#pragma unroll
            for (int r = 0; r < RPG; r++) HS0[r*HPAD + u] = hn[r];
        }
        barg(bid);

        // ================= layer 1 =================
        if (act) {
#pragma unroll
            for (int r = 0; r < RPG; r++) { zi[r]=0; zf[r]=0; zg[r]=0; zo[r]=0; }
            accH<5000>(zi, zf, zg, zo, sm + W1IA_OFF, HS0, u);
            accH<5000>(zi, zf, zg, zo, sm + W1RA_OFF, HS1, u);
#pragma unroll
            for (int r = 0; r < RPG; r++) {
                float a, b;
                unpack2(zi[r], a, b); const float si = a + b + bi1;
                unpack2(zf[r], a, b); const float sf = a + b + bf1;
                unpack2(zg[r], a, b); const float sg = a + b + bg1;
                unpack2(zo[r], a, b); const float so = a + b + bo1;
                const float ig = sigmoidf_(si);
                const float fg = sigmoidf_(sf);
                const float gg = tanhf_(sg);
                const float og = sigmoidf_(so);
                c1[r] = fg * c1[r] + ig * gg;
                hn[r] = og * tanhf_(c1[r]);
            }
        }
        barg(bid);
        if (act) {
#pragma unroll
            for (int r = 0; r < RPG; r++) HS1[r*HPAD + u] = hn[r];
        }
        barg(bid);

        // ================= layer 2 =================
        if (act) {
#pragma unroll
            for (int r = 0; r < RPG; r++) { zi[r]=0; zf[r]=0; zg[r]=0; zo[r]=0; }
            accH<5000>(zi, zf, zg, zo, sm + W2IA_OFF, HS1, u);
            accH<5000>(zi, zf, zg, zo, sm + W2RA_OFF, HS2, u);
#pragma unroll
            for (int r = 0; r < RPG; r++) {
                float a, b;
                unpack2(zi[r], a, b); const float si = a + b + bi2;
                unpack2(zf[r], a, b); const float sf = a + b + bf2;
                unpack2(zg[r], a, b); const float sg = a + b + bg2;
                unpack2(zo[r], a, b); const float so = a + b + bo2;
                const float ig = sigmoidf_(si);
                const float fg = sigmoidf_(sf);
                const float gg = tanhf_(sg);
                const float og = sigmoidf_(so);
                c2[r] = fg * c2[r] + ig * gg;
                hn[r] = og * tanhf_(c2[r]);
            }
        }
        barg(bid);
        if (act) {
#pragma unroll
            for (int r = 0; r < RPG; r++) HS2[r*HPAD + u] = hn[r];
        }
        barg(bid);
    }

    __syncthreads();

    // ---- final linear: out[b] = h2[b] . Wlin + blin ----
    if (tid < BC) {
        float s = blin[0];
#pragma unroll 10
        for (int uu = 0; uu < Hn; uu++)
            s += HS[2*(BC*HPAD) + tid*HPAD + uu] * Wlin[uu];
        out[bbase + tid] = s;
    }
}

extern "C" void kernel_launch(void* const* d_in, const int* in_sizes, int n_in,
                              void* d_out, int out_size)
{
    (void)in_sizes; (void)n_in; (void)out_size;
    const float* x    = (const float*)d_in[0];
    const float* Wih0 = (const float*)d_in[1];
    const float* Whh0 = (const float*)d_in[2];
    const float* bih0 = (const float*)d_in[3];
    const float* bhh0 = (const float*)d_in[4];
    const float* Wih1 = (const float*)d_in[5];
    const float* Whh1 = (const float*)d_in[6];
    const float* bih1 = (const float*)d_in[7];
    const float* bhh1 = (const float*)d_in[8];
    const float* Wih2 = (const float*)d_in[9];
    const float* Whh2 = (const float*)d_in[10];
    const float* bih2 = (const float*)d_in[11];
    const float* bhh2 = (const float*)d_in[12];
    const float* Wlin = (const float*)d_in[13];
    const float* blin = (const float*)d_in[14];
    float* out = (float*)d_out;

    cudaFuncSetAttribute(lstm_fused, cudaFuncAttributeMaxDynamicSharedMemorySize, SMEM_BYTES);
    lstm_fused<<<Bn / BC, NTHREADS, SMEM_BYTES>>>(
        x, Wih0, Whh0, bih0, bhh0,
        Wih1, Whh1, bih1, bhh1,
        Wih2, Whh2, bih2, bhh2,
        Wlin, blin, out);
}

// round 10
// speedup vs baseline: 1.2548x; 1.2548x over previous
#include <cuda_runtime.h>

// Problem constants
#define Tn 336
#define Fn 12
#define Hn 50
#define Bn 4096
#define BC 32          // batch rows per CTA
#define NTHREADS 512
#define RPG 4          // rows per group (8 groups x 2 warps)
#define HPAD 52        // non-dup h2 row stride (floats)
#define HDUP 100       // duplicated h row stride (floats): [h0,h0,h1,h1,...]

// shared memory float offsets (weights in [j][u][4-gates] layout, 16B per (j,u))
#define W0H_OFF 0        // layer0 recurrent  [50][50][4] = 10000
#define W1I_OFF 10000    // layer1 input(h0)
#define W1R_OFF 20000    // layer1 recurrent(h1)
#define W2I_OFF 30000    // layer2 input(h1)
#define W2R_OFF 40000    // layer2 recurrent(h2)
#define HD0_OFF 50000    // h0 duplicated: 32*100 = 3200
#define HD1_OFF 53200    // h1 duplicated: 3200
#define HS2_OFF 56400    // h2 normal: 32*52 = 1664
#define SMEM_FLOATS 58064
#define SMEM_BYTES (SMEM_FLOATS * 4)   // 232,256 <= 232,448

#define BT (Bn * Tn)   // 1,376,256

// precomputed layer-0 input projection (+bias), layout [bt][u][4 gates i,f,g,o]
__device__ float g_xz0[(size_t)BT * 200];

typedef unsigned long long u64;

// packed dual-fp32 FMA (sm_103a FFMA2)
__device__ __forceinline__ void ffma2(u64& z, const u64 w, const u64 h) {
    asm("fma.rn.f32x2 %0, %1, %2, %0;" : "+l"(z) : "l"(w), "l"(h));
}
__device__ __forceinline__ u64 dup2(const float s) {
    u64 r; asm("mov.b64 %0, {%1, %1};" : "=l"(r) : "f"(s)); return r;
}
__device__ __forceinline__ u64 pack2(const float lo, const float hi) {
    u64 r; asm("mov.b64 %0, {%1, %2};" : "=l"(r) : "f"(lo), "f"(hi)); return r;
}
__device__ __forceinline__ void unpack2(const u64 v, float& lo, float& hi) {
    asm("mov.b64 {%0, %1}, %2;" : "=f"(lo), "=f"(hi) : "l"(v));
}

__device__ __forceinline__ float sigmoidf_(float v) {
    return 1.0f / (1.0f + __expf(-v));
}
__device__ __forceinline__ float tanhf_(float v) {
    const float e = __expf(2.0f * v);
    return 1.0f - 2.0f / (e + 1.0f);
}

// named barrier for a 2-warp group (ids 1..8)
__device__ __forceinline__ void barg(int id) {
    asm volatile("bar.sync %0, 64;" :: "r"(id) : "memory");
}

struct Z2 { u64 a, b; };   // a = (i,f), b = (g,o)

// z += sum_{j<50} W[j][u][:] * h[j], h from DUPLICATED storage (stride HDUP).
// No dup MOVs: each LDS.128 of hd yields two (h,h) u64 operands directly.
__device__ __forceinline__ void accD(Z2 z[RPG], const float* __restrict__ W,
                                     const float* __restrict__ hd, int u)
{
    const float* w  = W + u*4;
    const float* hq = hd;
#pragma unroll 1
    for (int jb = 0; jb < 48; jb += 4) {
        const ulonglong2 w0 = *(const ulonglong2*)(w);
        const ulonglong2 w1 = *(const ulonglong2*)(w + 200);
        const ulonglong2 w2 = *(const ulonglong2*)(w + 400);
        const ulonglong2 w3 = *(const ulonglong2*)(w + 600);
#pragma unroll
        for (int r = 0; r < RPG; r++) {
            const ulonglong2 d01 = *(const ulonglong2*)(hq + r*HDUP);      // (hj,hj),(hj1,hj1)
            const ulonglong2 d23 = *(const ulonglong2*)(hq + r*HDUP + 4);
            ffma2(z[r].a, w0.x, d01.x); ffma2(z[r].b, w0.y, d01.x);
            ffma2(z[r].a, w1.x, d01.y); ffma2(z[r].b, w1.y, d01.y);
            ffma2(z[r].a, w2.x, d23.x); ffma2(z[r].b, w2.y, d23.x);
            ffma2(z[r].a, w3.x, d23.y); ffma2(z[r].b, w3.y, d23.y);
        }
        w += 800; hq += 8;
    }
    // remainder j = 48,49  (hq is now at +96 = 2*48)
    const ulonglong2 w0 = *(const ulonglong2*)(w);
    const ulonglong2 w1 = *(const ulonglong2*)(w + 200);
#pragma unroll
    for (int r = 0; r < RPG; r++) {
        const ulonglong2 d01 = *(const ulonglong2*)(hq + r*HDUP);
        ffma2(z[r].a, w0.x, d01.x); ffma2(z[r].b, w0.y, d01.x);
        ffma2(z[r].a, w1.x, d01.y); ffma2(z[r].b, w1.y, d01.y);
    }
}

// z += sum_{j<50} W[j][u][:] * h[j], h from NORMAL storage (stride HPAD), dup2 in regs.
__device__ __forceinline__ void accR(Z2 z[RPG], const float* __restrict__ W,
                                     const float* __restrict__ hb, int u)
{
    const float* w  = W + u*4;
    const float* hq = hb;
#pragma unroll 1
    for (int jb = 0; jb < 48; jb += 4) {
        const ulonglong2 w0 = *(const ulonglong2*)(w);
        const ulonglong2 w1 = *(const ulonglong2*)(w + 200);
        const ulonglong2 w2 = *(const ulonglong2*)(w + 400);
        const ulonglong2 w3 = *(const ulonglong2*)(w + 600);
#pragma unroll
        for (int r = 0; r < RPG; r++) {
            const float4 hv = *(const float4*)(hq + r*HPAD);
            const u64 h0 = dup2(hv.x);
            const u64 h1 = dup2(hv.y);
            const u64 h2 = dup2(hv.z);
            const u64 h3 = dup2(hv.w);
            ffma2(z[r].a, w0.x, h0); ffma2(z[r].b, w0.y, h0);
            ffma2(z[r].a, w1.x, h1); ffma2(z[r].b, w1.y, h1);
            ffma2(z[r].a, w2.x, h2); ffma2(z[r].b, w2.y, h2);
            ffma2(z[r].a, w3.x, h3); ffma2(z[r].b, w3.y, h3);
        }
        w += 800; hq += 4;   // NORMAL storage: 4 floats per 4 j's (was the OOB bug)
    }
    // remainder j = 48,49  (hq is now at +48)
    const ulonglong2 w0 = *(const ulonglong2*)(w);
    const ulonglong2 w1 = *(const ulonglong2*)(w + 200);
#pragma unroll
    for (int r = 0; r < RPG; r++) {
        const u64 h48 = dup2(hq[r*HPAD]);
        const u64 h49 = dup2(hq[r*HPAD + 1]);
        ffma2(z[r].a, w0.x, h48); ffma2(z[r].b, w0.y, h48);
        ffma2(z[r].a, w1.x, h49); ffma2(z[r].b, w1.y, h49);
    }
}

// =================== precompute: xz0 = x @ Wih0^T + (bih0 + bhh0) ===================
__global__ void __launch_bounds__(256, 4)
xproj_kernel(const float* __restrict__ x, const float* __restrict__ Wih0,
             const float* __restrict__ bih0, const float* __restrict__ bhh0)
{
    __shared__ float wsm[200 * 13];   // padded rows (conflict-free)
    __shared__ float bsm[200];
    const int tid = threadIdx.x;
    for (int i = tid; i < 2400; i += 256) {
        const int row = i / 12, k = i % 12;
        wsm[row*13 + k] = Wih0[i];
    }
    for (int i = tid; i < 200; i += 256) bsm[i] = bih0[i] + bhh0[i];
    __syncthreads();

    const long long base = (long long)blockIdx.x * 2048 + tid;  // over BT*50 groups
#pragma unroll 1
    for (int it = 0; it < 8; it++) {
        const long long n = base + (long long)it * 256;
        if (n < (long long)BT * 50) {
            const long long bt = n / 50;
            const int u = (int)(n % 50);
            const float4* xr = (const float4*)(x + bt * 12);
            const float4 x0 = xr[0], x1 = xr[1], x2 = xr[2];
            float acc[4];
#pragma unroll
            for (int g = 0; g < 4; g++) {
                const float* wr = wsm + (g*50 + u) * 13;
                float s = bsm[g*50 + u];
                s += wr[0]*x0.x + wr[1]*x0.y + wr[2]*x0.z  + wr[3]*x0.w;
                s += wr[4]*x1.x + wr[5]*x1.y + wr[6]*x1.z  + wr[7]*x1.w;
                s += wr[8]*x2.x + wr[9]*x2.y + wr[10]*x2.z + wr[11]*x2.w;
                acc[g] = s;
            }
            *(float4*)(g_xz0 + (size_t)n * 4) = make_float4(acc[0], acc[1], acc[2], acc[3]);
        }
    }
}

// =================== main fused LSTM ===================
__global__ void __launch_bounds__(NTHREADS, 1)
lstm_fused(const float* __restrict__ Whh0,
           const float* __restrict__ Wih1, const float* __restrict__ Whh1,
           const float* __restrict__ bih1, const float* __restrict__ bhh1,
           const float* __restrict__ Wih2, const float* __restrict__ Whh2,
           const float* __restrict__ bih2, const float* __restrict__ bhh2,
           const float* __restrict__ Wlin, const float* __restrict__ blin,
           float* __restrict__ out)
{
    extern __shared__ float sm[];

    const int tid   = threadIdx.x;
    const int lane  = tid & 31;
    const int wid   = tid >> 5;
    const int grp   = wid >> 1;               // 0..7
    const int bid   = grp + 1;                // named barrier id
    const int r0    = grp * RPG;              // row base (4 rows)
    const int u     = (wid & 1) * 32 + lane;  // unit id
    const bool act  = (u < Hn);

    // ---- stage weights: [j][u][4 gates] ----
    {
        const float* srcs[5] = { Whh0, Wih1, Whh1, Wih2, Whh2 };
        const int offs[5] = { W0H_OFF, W1I_OFF, W1R_OFF, W2I_OFF, W2R_OFF };
#pragma unroll 1
        for (int s = 0; s < 5; s++) {
            const float* Wsrc = srcs[s];
            float* A = sm + offs[s];
            for (int idx = tid; idx < 10000; idx += NTHREADS) {
                const int g  = idx & 3;
                const int uu = (idx >> 2) % 50;
                const int j  = idx / 200;
                A[idx] = Wsrc[(g*50 + uu)*50 + j];
            }
        }
    }
    // zero all h state (dup + normal)
    for (int idx = tid; idx < SMEM_FLOATS - HD0_OFF; idx += NTHREADS)
        sm[HD0_OFF + idx] = 0.0f;

    // biases for layers 1,2 as packed z inits
    u64 b1a = 0, b1b = 0, b2a = 0, b2b = 0;
    if (act) {
        b1a = pack2(bih1[u]       + bhh1[u],       bih1[50 + u]  + bhh1[50 + u]);
        b1b = pack2(bih1[100 + u] + bhh1[100 + u], bih1[150 + u] + bhh1[150 + u]);
        b2a = pack2(bih2[u]       + bhh2[u],       bih2[50 + u]  + bhh2[50 + u]);
        b2b = pack2(bih2[100 + u] + bhh2[100 + u], bih2[150 + u] + bhh2[150 + u]);
    }

    float c0[RPG], c1[RPG], c2[RPG];
#pragma unroll
    for (int r = 0; r < RPG; r++) { c0[r] = 0.f; c1[r] = 0.f; c2[r] = 0.f; }

    const long long bbase = (long long)blockIdx.x * BC;
    // xz0 pointer for this thread's rows; row r adds r*Tn*200 (const), t adds 200
    const float* xz = g_xz0 + ((size_t)(bbase + r0) * Tn) * 200 + (size_t)u * 4;

    __syncthreads();

    float* HD0 = sm + HD0_OFF + r0*HDUP;
    float* HD1 = sm + HD1_OFF + r0*HDUP;
    float* HS2 = sm + HS2_OFF + r0*HPAD;

    for (int t = 0; t < Tn; t++) {
        float hn[RPG];
        Z2 z[RPG];

        // ================= layer 0 =================
        if (act) {
            // z init = precomputed x-projection (+bias) : one LDG.128 per row
#pragma unroll
            for (int r = 0; r < RPG; r++) {
                const ulonglong2 v = *(const ulonglong2*)(xz + (size_t)r * (Tn*200));
                z[r].a = v.x; z[r].b = v.y;
            }
            accD(z, sm + W0H_OFF, HD0, u);
#pragma unroll
            for (int r = 0; r < RPG; r++) {
                float zi, zf, zg, zo;
                unpack2(z[r].a, zi, zf);
                unpack2(z[r].b, zg, zo);
                const float ig = sigmoidf_(zi);
                const float fg = sigmoidf_(zf);
                const float gg = tanhf_(zg);
                const float og = sigmoidf_(zo);
                c0[r] = fg * c0[r] + ig * gg;
                hn[r] = og * tanhf_(c0[r]);
            }
        }
        barg(bid);
        if (act) {
#pragma unroll
            for (int r = 0; r < RPG; r++)
                *(float2*)(HD0 + r*HDUP + 2*u) = make_float2(hn[r], hn[r]);
        }
        barg(bid);

        // ================= layer 1 =================
        if (act) {
#pragma unroll
            for (int r = 0; r < RPG; r++) { z[r].a = b1a; z[r].b = b1b; }
            accD(z, sm + W1I_OFF, HD0, u);
            accD(z, sm + W1R_OFF, HD1, u);
#pragma unroll
            for (int r = 0; r < RPG; r++) {
                float zi, zf, zg, zo;
                unpack2(z[r].a, zi, zf);
                unpack2(z[r].b, zg, zo);
                const float ig = sigmoidf_(zi);
                const float fg = sigmoidf_(zf);
                const float gg = tanhf_(zg);
                const float og = sigmoidf_(zo);
                c1[r] = fg * c1[r] + ig * gg;
                hn[r] = og * tanhf_(c1[r]);
            }
        }
        barg(bid);
        if (act) {
#pragma unroll
            for (int r = 0; r < RPG; r++)
                *(float2*)(HD1 + r*HDUP + 2*u) = make_float2(hn[r], hn[r]);
        }
        barg(bid);

        // ================= layer 2 =================
        if (act) {
#pragma unroll
            for (int r = 0; r < RPG; r++) { z[r].a = b2a; z[r].b = b2b; }
            accD(z, sm + W2I_OFF, HD1, u);
            accR(z, sm + W2R_OFF, HS2, u);
#pragma unroll
            for (int r = 0; r < RPG; r++) {
                float zi, zf, zg, zo;
                unpack2(z[r].a, zi, zf);
                unpack2(z[r].b, zg, zo);
                const float ig = sigmoidf_(zi);
                const float fg = sigmoidf_(zf);
                const float gg = tanhf_(zg);
                const float og = sigmoidf_(zo);
                c2[r] = fg * c2[r] + ig * gg;
                hn[r] = og * tanhf_(c2[r]);
            }
        }
        barg(bid);
        if (act) {
#pragma unroll
            for (int r = 0; r < RPG; r++) HS2[r*HPAD + u] = hn[r];
        }
        barg(bid);

        xz += 200;
    }

    __syncthreads();

    // ---- final linear: out[b] = h2[b] . Wlin + blin ----
    if (tid < BC) {
        float s = blin[0];
#pragma unroll 10
        for (int uu = 0; uu < Hn; uu++)
            s += sm[HS2_OFF + tid*HPAD + uu] * Wlin[uu];
        out[bbase + tid] = s;
    }
}

extern "C" void kernel_launch(void* const* d_in, const int* in_sizes, int n_in,
                              void* d_out, int out_size)
{
    (void)in_sizes; (void)n_in; (void)out_size;
    const float* x    = (const float*)d_in[0];
    const float* Wih0 = (const float*)d_in[1];
    const float* Whh0 = (const float*)d_in[2];
    const float* bih0 = (const float*)d_in[3];
    const float* bhh0 = (const float*)d_in[4];
    const float* Wih1 = (const float*)d_in[5];
    const float* Whh1 = (const float*)d_in[6];
    const float* bih1 = (const float*)d_in[7];
    const float* bhh1 = (const float*)d_in[8];
    const float* Wih2 = (const float*)d_in[9];
    const float* Whh2 = (const float*)d_in[10];
    const float* bih2 = (const float*)d_in[11];
    const float* bhh2 = (const float*)d_in[12];
    const float* Wlin = (const float*)d_in[13];
    const float* blin = (const float*)d_in[14];
    float* out = (float*)d_out;

    // layer-0 input projection for all (b,t): 68,812,800 outputs-of-4 / 2048 per block
    xproj_kernel<<<33600, 256>>>(x, Wih0, bih0, bhh0);

    cudaFuncSetAttribute(lstm_fused, cudaFuncAttributeMaxDynamicSharedMemorySize, SMEM_BYTES);
    lstm_fused<<<Bn / BC, NTHREADS, SMEM_BYTES>>>(
        Whh0,
        Wih1, Whh1, bih1, bhh1,
        Wih2, Whh2, bih2, bhh2,
        Wlin, blin, out);
}